// round 16
// baseline (speedup 1.0000x reference)
#include <cuda_runtime.h>
#include <cuda_fp16.h>
#include <cstdint>
#include <math.h>

#define N 49
#define CH 128
#define NH 4
#define DH 32

// ============================ scratch ============================
__device__ uint32_t g_wfrag[3 * 8192];     // W fp16 fragments [m][nt][ks][np][lane][q]
__device__ float2   g_bias2[NH * 2048];    // bias [h][mt][nn][rp][lane] as (jA,jB)

// ============================ helpers ============================
__device__ __forceinline__ uint32_t smem_u32(const void* p) {
    uint32_t a;
    asm("{ .reg .u64 t; cvta.to.shared.u64 t, %1; cvt.u32.u64 %0, t; }" : "=r"(a) : "l"(p));
    return a;
}
__device__ __forceinline__ void ldsm_x4(uint32_t* r, uint32_t addr) {
    asm volatile("ldmatrix.sync.aligned.m8n8.x4.shared.b16 {%0,%1,%2,%3}, [%4];"
        : "=r"(r[0]), "=r"(r[1]), "=r"(r[2]), "=r"(r[3]) : "r"(addr));
}
__device__ __forceinline__ void mma16816f16(float* c, const uint32_t* a, uint32_t b0, uint32_t b1) {
    asm volatile(
        "mma.sync.aligned.m16n8k16.row.col.f32.f16.f16.f32 "
        "{%0,%1,%2,%3}, {%4,%5,%6,%7}, {%8,%9}, {%0,%1,%2,%3};"
        : "+f"(c[0]), "+f"(c[1]), "+f"(c[2]), "+f"(c[3])
        : "r"(a[0]), "r"(a[1]), "r"(a[2]), "r"(a[3]), "r"(b0), "r"(b1));
}
__device__ __forceinline__ uint32_t pack_h2(float a, float b) {
    __half2 h = __floats2half2_rn(a, b);
    return *reinterpret_cast<uint32_t*>(&h);
}

// ============================ prep ============================
__global__ void prep_kernel(const float* __restrict__ Wq, const float* __restrict__ Wk,
                            const float* __restrict__ Wv,
                            const float* __restrict__ table, const void* __restrict__ idx_raw) {
    const int blk = blockIdx.x;
    const int tid = threadIdx.x;
    if (blk < 3) {
        const float* W = (blk == 0) ? Wq : ((blk == 1) ? Wk : Wv);
        for (int f = tid; f < 8192; f += 256) {
            int q    = f & 3;
            int lane = (f >> 2) & 31;
            int np   = (f >> 7) & 1;
            int ks   = (f >> 8) & 7;
            int nt   = (f >> 11) & 3;
            int n = nt * 32 + np * 16 + (q >> 1) * 8 + (lane >> 2);
            int k = ks * 16 + (q & 1) * 8 + 2 * (lane & 3);
            g_wfrag[blk * 8192 + f] = pack_h2(W[n * 128 + k], W[n * 128 + k + 1]);
        }
    } else {
        const int h = blk - 3;
        // dtype-robust: int64-declared indices that JAX (x64 off) emits as int32
        __shared__ int is32;
        const int* i32 = (const int*)idx_raw;
        if (tid == 0) is32 = 0;
        __syncthreads();
        int any = 0;
        for (int t = tid; t < N * N; t += 256)
            if ((t & 1) && i32[t] != 0) any = 1;
        if (any) is32 = 1;
        __syncthreads();
        const int stride = is32 ? 1 : 2;
        // layout: h*2048 + mt*512 + nn*64 + rp*32 + lane (matches consumer)
        for (int f = tid; f < 2048; f += 256) {
            int lane = f & 31;
            int rp   = (f >> 5) & 1;
            int nn   = (f >> 6) & 7;
            int mt   = (f >> 9) & 3;
            int i  = mt * 16 + rp * 8 + (lane >> 2);
            int jA = nn * 8 + 2 * (lane & 3);
            float x = 0.f, y = 0.f;
            if (i < N) {
                if (jA < N)     x = table[i32[(i * N + jA) * stride] * NH + h];
                if (jA + 1 < N) y = table[i32[(i * N + jA + 1) * stride] * NH + h];
            }
            g_bias2[h * 2048 + f] = make_float2(x, y);
        }
    }
}

// ============================ fused kernel (2 CTAs/SM) ============================
// smem byte layout (97040 B):
//  HOFF   = 0     : hidden fp16, 64 x 272B = 17408 (rows 49..63 zero)
//  KOFF   = 17408 : K fp16 [h][j 64][d2 16] words, pitch 80B -> 20480
//  VTOFF  = 37888 : V^T fp16 [h][c 32][j 72] halves, pitch 144B -> 18432
//  MASKOFF= 56320 : mask fp32 pitch 52 -> 13312
//  BIOFF  = 69632 : qkv bias fp32 [384] -> 1536
//  OUTOFF = 71168 : ctx staging fp32 [49][132] -> 25872
#define HOFF    0
#define KOFF    17408
#define VTOFF   37888
#define MASKOFF 56320
#define BIOFF   69632
#define OUTOFF  71168
#define FSMEM_BYTES 97040

__global__ void __launch_bounds__(512, 2)
fused_kernel(const float* __restrict__ hs, const float* __restrict__ mask,
             const float* __restrict__ bq, const float* __restrict__ bk,
             const float* __restrict__ bv, float* __restrict__ out)
{
    extern __shared__ char smem[];
    const uint32_t sb = smem_u32(smem);
    const int b = blockIdx.x;
    const int t = threadIdx.x;
    const int lane = t & 31;
    const int warp = t >> 5;

    float* sBiasF = reinterpret_cast<float*>(smem + BIOFF);
    float* sMask  = reinterpret_cast<float*>(smem + MASKOFF);
    float* sOut   = reinterpret_cast<float*>(smem + OUTOFF);

    // ---- stage hidden (fp16, pitch 272), mask (pitch 52), qkv biases ----
    {
        const float2* hsb = reinterpret_cast<const float2*>(hs + (size_t)b * (N * CH));
        for (int e = t; e < 64 * 64; e += 512) {
            int row = e >> 6, kp = e & 63;
            float2 x = (row < N) ? hsb[row * 64 + kp] : make_float2(0.f, 0.f);
            *reinterpret_cast<uint32_t*>(smem + HOFF + row * 272 + kp * 4) = pack_h2(x.x, x.y);
        }
    }
    {
        const float* mb = mask + (size_t)b * (N * N);
        for (int e = t; e < N * N; e += 512) {
            int i = e / N, j = e - i * N;
            sMask[i * 52 + j] = mb[e];
        }
    }
    if (t < 384)
        sBiasF[t] = (t < 128) ? bq[t] : ((t < 256) ? bk[t - 128] : bv[t - 256]);
    __syncthreads();

    const int g  = lane >> 2;
    const int tg = lane & 3;
    const uint32_t a_row = (uint32_t)((lane & 7) + ((lane >> 3) & 1) * 8);
    const uint32_t a_kb  = (uint32_t)((lane >> 4) * 16);
    const uint32_t b_row = (uint32_t)((lane & 7) + (lane >> 4) * 8);
    const uint32_t b_kb  = (uint32_t)(((lane >> 3) & 1) * 16);

    const int mt = warp & 3;       // i-tile
    const int nt = warp >> 2;      // n-tile == head
    const int i0 = mt * 16 + g;
    const int i1 = i0 + 8;

    // ---- A fragments: load once, reuse for all 3 GEMMs ----
    uint32_t ahc[8][4];
    {
        const uint32_t aBase = sb + HOFF + (mt * 16 + a_row) * 272 + a_kb;
#pragma unroll
        for (int ks = 0; ks < 8; ks++)
            ldsm_x4(ahc[ks], aBase + ks * 32);
    }

    uint32_t qlo[4], qhi[4];

    // ---- QKV GEMM: order K, V, Q; W read directly as fragments ----
    const int morder[3] = {1, 2, 0};
#pragma unroll 1
    for (int it = 0; it < 3; it++) {
        const int m = morder[it];
        float acc[4][4];
#pragma unroll
        for (int q = 0; q < 4; q++)
#pragma unroll
            for (int r = 0; r < 4; r++) acc[q][r] = 0.f;

        const uint4* wfm = reinterpret_cast<const uint4*>(g_wfrag + m * 8192) + nt * 512 + lane;
#pragma unroll
        for (int ks = 0; ks < 8; ks++) {
#pragma unroll
            for (int np = 0; np < 2; np++) {
                uint4 bw = wfm[(ks * 2 + np) * 32];
                mma16816f16(acc[2 * np],     ahc[ks], bw.x, bw.y);
                mma16816f16(acc[2 * np + 1], ahc[ks], bw.z, bw.w);
            }
        }

        const float* bF = sBiasF + m * 128;
        if (m == 1) {
            uint32_t* dst = reinterpret_cast<uint32_t*>(smem + KOFF);
#pragma unroll
            for (int q = 0; q < 4; q++) {
                int n = nt * 32 + q * 8 + 2 * tg;
                int d2 = (n >> 1) & 15;
                float b0 = bF[n], b1 = bF[n + 1];
                dst[nt * 1280 + i0 * 20 + d2] = pack_h2(acc[q][0] + b0, acc[q][1] + b1);
                dst[nt * 1280 + i1 * 20 + d2] = pack_h2(acc[q][2] + b0, acc[q][3] + b1);
            }
        } else if (m == 2) {
            __half* vt = reinterpret_cast<__half*>(smem + VTOFF);
#pragma unroll
            for (int q = 0; q < 4; q++) {
                int n = nt * 32 + q * 8 + 2 * tg;
                int c = n & 31;
                float b0 = bF[n], b1 = bF[n + 1];
                vt[nt * 2304 + c * 72 + i0]       = __float2half(acc[q][0] + b0);
                vt[nt * 2304 + (c + 1) * 72 + i0] = __float2half(acc[q][1] + b1);
                vt[nt * 2304 + c * 72 + i1]       = __float2half(acc[q][2] + b0);
                vt[nt * 2304 + (c + 1) * 72 + i1] = __float2half(acc[q][3] + b1);
            }
        } else {  // m == 0: Q stays in registers
#pragma unroll
            for (int q = 0; q < 4; q++) {
                int n = nt * 32 + q * 8 + 2 * tg;
                float b0 = bF[n], b1 = bF[n + 1];
                qlo[q] = pack_h2(acc[q][0] + b0, acc[q][1] + b1);
                qhi[q] = pack_h2(acc[q][2] + b0, acc[q][3] + b1);
            }
        }
    }
    __syncthreads();  // K / V^T visible to all warps

    const int h = nt;
    const float rscale = 0.17677669529663687f;
    const size_t tb = (size_t)b * N;

    // ---- scores: Q (register A-fragments) x K^T ----
    float sc[8][4];
#pragma unroll
    for (int nn = 0; nn < 8; nn++)
#pragma unroll
        for (int r = 0; r < 4; r++) sc[nn][r] = 0.f;
    {
        const uint32_t kbase = sb + KOFF + h * 5120 + b_row * 80 + b_kb;
#pragma unroll
        for (int kc = 0; kc < 2; kc++) {
            uint32_t ah[4];
            ah[0] = qlo[2 * kc];
            ah[1] = qhi[2 * kc];
            ah[2] = qlo[2 * kc + 1];
            ah[3] = qhi[2 * kc + 1];
#pragma unroll
            for (int np = 0; np < 4; np++) {
                uint32_t bh[4];
                ldsm_x4(bh, kbase + (uint32_t)(np * 16 * 80) + kc * 32);
                mma16816f16(sc[2 * np],     ah, bh[0], bh[1]);
                mma16816f16(sc[2 * np + 1], ah, bh[2], bh[3]);
            }
        }
    }

    // ---- fix-up: coalesced fragment-ordered bias LDG + smem mask float2 ----
    const float2* b2 = g_bias2 + h * 2048 + mt * 512 + lane;  // + (nn*2+rp)*32
    const float2* mk2 = reinterpret_cast<const float2*>(sMask);
    const bool i0v = i0 < N, i1v = i1 < N;
#pragma unroll
    for (int nn = 0; nn < 8; nn++) {
        int jA = nn * 8 + 2 * tg;
        int jB = jA + 1;
        bool jAv = jA < N, jBv = jB < N;
        float2 fb0 = b2[(nn * 2 + 0) * 32];
        float2 fb1 = b2[(nn * 2 + 1) * 32];
        float2 fm0 = mk2[(i0 * 52 + jA) >> 1];
        float2 fm1 = mk2[(i1 * 52 + jA) >> 1];
        sc[nn][0] = (i0v && jAv) ? sc[nn][0] * rscale + fb0.x + fm0.x : -1e30f;
        sc[nn][1] = (i0v && jBv) ? sc[nn][1] * rscale + fb0.y + fm0.y : -1e30f;
        sc[nn][2] = (i1v && jAv) ? sc[nn][2] * rscale + fb1.x + fm1.x : -1e30f;
        sc[nn][3] = (i1v && jBv) ? sc[nn][3] * rscale + fb1.y + fm1.y : -1e30f;
    }

    // ---- register softmax ----
    float mx0 = -1e30f, mx1 = -1e30f;
#pragma unroll
    for (int nn = 0; nn < 8; nn++) {
        mx0 = fmaxf(mx0, fmaxf(sc[nn][0], sc[nn][1]));
        mx1 = fmaxf(mx1, fmaxf(sc[nn][2], sc[nn][3]));
    }
    mx0 = fmaxf(mx0, __shfl_xor_sync(0xffffffffu, mx0, 1));
    mx0 = fmaxf(mx0, __shfl_xor_sync(0xffffffffu, mx0, 2));
    mx1 = fmaxf(mx1, __shfl_xor_sync(0xffffffffu, mx1, 1));
    mx1 = fmaxf(mx1, __shfl_xor_sync(0xffffffffu, mx1, 2));

    float sum0 = 0.f, sum1 = 0.f;
#pragma unroll
    for (int nn = 0; nn < 8; nn++) {
        sc[nn][0] = __expf(sc[nn][0] - mx0);
        sc[nn][1] = __expf(sc[nn][1] - mx0);
        sc[nn][2] = __expf(sc[nn][2] - mx1);
        sc[nn][3] = __expf(sc[nn][3] - mx1);
        sum0 += sc[nn][0] + sc[nn][1];
        sum1 += sc[nn][2] + sc[nn][3];
    }
    sum0 += __shfl_xor_sync(0xffffffffu, sum0, 1);
    sum0 += __shfl_xor_sync(0xffffffffu, sum0, 2);
    sum1 += __shfl_xor_sync(0xffffffffu, sum1, 1);
    sum1 += __shfl_xor_sync(0xffffffffu, sum1, 2);
    const float inv0 = 1.0f / sum0;
    const float inv1 = 1.0f / sum1;

    // ---- ctx: P (register A-fragments) x V^T; stage to sOut (conflict-free STS.64) ----
    const uint32_t vbase = sb + VTOFF + h * 4608 + b_row * 144 + b_kb;
#pragma unroll
    for (int np = 0; np < 2; np++) {
        float ct[2][4];
#pragma unroll
        for (int q = 0; q < 2; q++)
#pragma unroll
            for (int r = 0; r < 4; r++) ct[q][r] = 0.f;
#pragma unroll
        for (int kc = 0; kc < 4; kc++) {
            uint32_t a[4];
            a[0] = pack_h2(sc[2 * kc][0] * inv0,     sc[2 * kc][1] * inv0);
            a[1] = pack_h2(sc[2 * kc][2] * inv1,     sc[2 * kc][3] * inv1);
            a[2] = pack_h2(sc[2 * kc + 1][0] * inv0, sc[2 * kc + 1][1] * inv0);
            a[3] = pack_h2(sc[2 * kc + 1][2] * inv1, sc[2 * kc + 1][3] * inv1);
            uint32_t bh[4];
            ldsm_x4(bh, vbase + (uint32_t)(np * 16 * 144) + kc * 32);
            mma16816f16(ct[0], a, bh[0], bh[1]);
            mma16816f16(ct[1], a, bh[2], bh[3]);
        }
#pragma unroll
        for (int q = 0; q < 2; q++) {
            int c = h * 32 + np * 16 + q * 8 + 2 * tg;
            if (i0v)
                *reinterpret_cast<float2*>(&sOut[i0 * 132 + c]) = make_float2(ct[q][0], ct[q][1]);
            if (i1v)
                *reinterpret_cast<float2*>(&sOut[i1 * 132 + c]) = make_float2(ct[q][2], ct[q][3]);
        }
    }
    __syncthreads();  // sOut complete

    // ---- coalesced output store ----
    {
        float* ob = out + tb * CH;
        for (int e = t; e < N * CH; e += 512) {
            int i = e >> 7, j = e & 127;
            ob[e] = sOut[i * 132 + j];
        }
    }
}

// ============================ launch ============================
extern "C" void kernel_launch(void* const* d_in, const int* in_sizes, int n_in,
                              void* d_out, int out_size) {
    const float* hs    = (const float*)d_in[0];
    const float* mask  = (const float*)d_in[1];
    const float* Wq    = (const float*)d_in[2];
    const float* bq    = (const float*)d_in[3];
    const float* Wk    = (const float*)d_in[4];
    const float* bk    = (const float*)d_in[5];
    const float* Wv    = (const float*)d_in[6];
    const float* bv    = (const float*)d_in[7];
    const float* table = (const float*)d_in[8];
    const void*  idx   = (const void*)d_in[9];
    float* out = (float*)d_out;

    int B = in_sizes[0] / (N * CH);

    cudaFuncSetAttribute(fused_kernel, cudaFuncAttributeMaxDynamicSharedMemorySize,
                         FSMEM_BYTES);

    prep_kernel<<<7, 256>>>(Wq, Wk, Wv, table, idx);
    fused_kernel<<<B, 512, FSMEM_BYTES>>>(hs, mask, bq, bk, bv, out);
}

// round 17
// speedup vs baseline: 1.0535x; 1.0535x over previous
#include <cuda_runtime.h>
#include <cuda_fp16.h>
#include <cstdint>
#include <math.h>

#define N 49
#define CH 128
#define NH 4
#define DH 32

// ============================ scratch ============================
__device__ uint32_t g_wfrag[3 * 8192];     // W fp16 fragments [m][nt][ks][np][lane][q]
__device__ float2   g_bias2[NH * 2048];    // bias [h][mt][nn][rp][lane] as (jA,jB)

// ============================ helpers ============================
__device__ __forceinline__ uint32_t smem_u32(const void* p) {
    uint32_t a;
    asm("{ .reg .u64 t; cvta.to.shared.u64 t, %1; cvt.u32.u64 %0, t; }" : "=r"(a) : "l"(p));
    return a;
}
__device__ __forceinline__ void ldsm_x4(uint32_t* r, uint32_t addr) {
    asm volatile("ldmatrix.sync.aligned.m8n8.x4.shared.b16 {%0,%1,%2,%3}, [%4];"
        : "=r"(r[0]), "=r"(r[1]), "=r"(r[2]), "=r"(r[3]) : "r"(addr));
}
__device__ __forceinline__ void mma16816f16(float* c, const uint32_t* a, uint32_t b0, uint32_t b1) {
    asm volatile(
        "mma.sync.aligned.m16n8k16.row.col.f32.f16.f16.f32 "
        "{%0,%1,%2,%3}, {%4,%5,%6,%7}, {%8,%9}, {%0,%1,%2,%3};"
        : "+f"(c[0]), "+f"(c[1]), "+f"(c[2]), "+f"(c[3])
        : "r"(a[0]), "r"(a[1]), "r"(a[2]), "r"(a[3]), "r"(b0), "r"(b1));
}
__device__ __forceinline__ uint32_t pack_h2(float a, float b) {
    __half2 h = __floats2half2_rn(a, b);
    return *reinterpret_cast<uint32_t*>(&h);
}

// ============================ prep ============================
__global__ void prep_kernel(const float* __restrict__ Wq, const float* __restrict__ Wk,
                            const float* __restrict__ Wv,
                            const float* __restrict__ table, const void* __restrict__ idx_raw) {
    const int blk = blockIdx.x;
    const int tid = threadIdx.x;
    if (blk < 3) {
        const float* W = (blk == 0) ? Wq : ((blk == 1) ? Wk : Wv);
        for (int f = tid; f < 8192; f += 256) {
            int q    = f & 3;
            int lane = (f >> 2) & 31;
            int np   = (f >> 7) & 1;
            int ks   = (f >> 8) & 7;
            int nt   = (f >> 11) & 3;
            int n = nt * 32 + np * 16 + (q >> 1) * 8 + (lane >> 2);
            int k = ks * 16 + (q & 1) * 8 + 2 * (lane & 3);
            g_wfrag[blk * 8192 + f] = pack_h2(W[n * 128 + k], W[n * 128 + k + 1]);
        }
    } else {
        const int h = blk - 3;
        // dtype-robust: int64-declared indices that JAX (x64 off) emits as int32
        __shared__ int is32;
        const int* i32 = (const int*)idx_raw;
        if (tid == 0) is32 = 0;
        __syncthreads();
        int any = 0;
        for (int t = tid; t < N * N; t += 256)
            if ((t & 1) && i32[t] != 0) any = 1;
        if (any) is32 = 1;
        __syncthreads();
        const int stride = is32 ? 1 : 2;
        // layout: h*2048 + mt*512 + nn*64 + rp*32 + lane (matches consumer)
        for (int f = tid; f < 2048; f += 256) {
            int lane = f & 31;
            int rp   = (f >> 5) & 1;
            int nn   = (f >> 6) & 7;
            int mt   = (f >> 9) & 3;
            int i  = mt * 16 + rp * 8 + (lane >> 2);
            int jA = nn * 8 + 2 * (lane & 3);
            float x = 0.f, y = 0.f;
            if (i < N) {
                if (jA < N)     x = table[i32[(i * N + jA) * stride] * NH + h];
                if (jA + 1 < N) y = table[i32[(i * N + jA + 1) * stride] * NH + h];
            }
            g_bias2[h * 2048 + f] = make_float2(x, y);
        }
    }
}

// ============================ fused kernel (2 CTAs/SM) ============================
// smem byte layout (71168 B):
//  HOFF   = 0     : hidden fp16, 64 x 272B = 17408 (rows 49..63 zero)
//  KOFF   = 17408 : K fp16 [h][j 64][d2 16] words, pitch 80B -> 20480
//  VTOFF  = 37888 : V^T fp16 [h][c 32][j 72] halves, pitch 144B -> 18432
//  MASKOFF= 56320 : mask fp32 pitch 52 -> 13312
//  BIOFF  = 69632 : qkv bias fp32 [384] -> 1536
#define HOFF    0
#define KOFF    17408
#define VTOFF   37888
#define MASKOFF 56320
#define BIOFF   69632
#define FSMEM_BYTES 71168

__global__ void __launch_bounds__(512, 2)
fused_kernel(const float* __restrict__ hs, const float* __restrict__ mask,
             const float* __restrict__ bq, const float* __restrict__ bk,
             const float* __restrict__ bv, float* __restrict__ out)
{
    extern __shared__ char smem[];
    const uint32_t sb = smem_u32(smem);
    const int b = blockIdx.x;
    const int t = threadIdx.x;
    const int lane = t & 31;
    const int warp = t >> 5;

    float* sBiasF = reinterpret_cast<float*>(smem + BIOFF);
    float* sMask  = reinterpret_cast<float*>(smem + MASKOFF);

    // ---- stage hidden (fp16, pitch 272), mask (pitch 52), qkv biases ----
    {
        const float2* hsb = reinterpret_cast<const float2*>(hs + (size_t)b * (N * CH));
        for (int e = t; e < 64 * 64; e += 512) {
            int row = e >> 6, kp = e & 63;
            float2 x = (row < N) ? hsb[row * 64 + kp] : make_float2(0.f, 0.f);
            *reinterpret_cast<uint32_t*>(smem + HOFF + row * 272 + kp * 4) = pack_h2(x.x, x.y);
        }
    }
    {
        const float* mb = mask + (size_t)b * (N * N);
        for (int e = t; e < N * N; e += 512) {
            int i = e / N, j = e - i * N;
            sMask[i * 52 + j] = mb[e];
        }
    }
    if (t < 384)
        sBiasF[t] = (t < 128) ? bq[t] : ((t < 256) ? bk[t - 128] : bv[t - 256]);
    __syncthreads();

    const int g  = lane >> 2;
    const int tg = lane & 3;
    const uint32_t a_row = (uint32_t)((lane & 7) + ((lane >> 3) & 1) * 8);
    const uint32_t a_kb  = (uint32_t)((lane >> 4) * 16);
    const uint32_t b_row = (uint32_t)((lane & 7) + (lane >> 4) * 8);
    const uint32_t b_kb  = (uint32_t)(((lane >> 3) & 1) * 16);

    const int mt = warp & 3;       // i-tile
    const int nt = warp >> 2;      // n-tile == head
    const int i0 = mt * 16 + g;
    const int i1 = i0 + 8;

    // ---- A fragments: load once, reuse for all 3 GEMMs ----
    uint32_t ahc[8][4];
    {
        const uint32_t aBase = sb + HOFF + (mt * 16 + a_row) * 272 + a_kb;
#pragma unroll
        for (int ks = 0; ks < 8; ks++)
            ldsm_x4(ahc[ks], aBase + ks * 32);
    }

    const float rscale = 0.17677669529663687f;  // 1/sqrt(32), folded into Q pack
    uint32_t qlo[4], qhi[4];

    // ---- QKV GEMM: order K, V, Q; FULL unroll so ptxas can software-pipeline
    //      the wfrag LDGs of later iterations behind current MMAs ----
    const int morder[3] = {1, 2, 0};
#pragma unroll
    for (int it = 0; it < 3; it++) {
        const int m = morder[it];
        float acc[4][4];
#pragma unroll
        for (int q = 0; q < 4; q++)
#pragma unroll
            for (int r = 0; r < 4; r++) acc[q][r] = 0.f;

        const uint4* wfm = reinterpret_cast<const uint4*>(g_wfrag + m * 8192) + nt * 512 + lane;
#pragma unroll
        for (int ks = 0; ks < 8; ks++) {
#pragma unroll
            for (int np = 0; np < 2; np++) {
                uint4 bw = wfm[(ks * 2 + np) * 32];
                mma16816f16(acc[2 * np],     ahc[ks], bw.x, bw.y);
                mma16816f16(acc[2 * np + 1], ahc[ks], bw.z, bw.w);
            }
        }

        const float* bF = sBiasF + m * 128;
        if (m == 1) {
            uint32_t* dst = reinterpret_cast<uint32_t*>(smem + KOFF);
#pragma unroll
            for (int q = 0; q < 4; q++) {
                int n = nt * 32 + q * 8 + 2 * tg;
                int d2 = (n >> 1) & 15;
                float b0 = bF[n], b1 = bF[n + 1];
                dst[nt * 1280 + i0 * 20 + d2] = pack_h2(acc[q][0] + b0, acc[q][1] + b1);
                dst[nt * 1280 + i1 * 20 + d2] = pack_h2(acc[q][2] + b0, acc[q][3] + b1);
            }
        } else if (m == 2) {
            __half* vt = reinterpret_cast<__half*>(smem + VTOFF);
#pragma unroll
            for (int q = 0; q < 4; q++) {
                int n = nt * 32 + q * 8 + 2 * tg;
                int c = n & 31;
                float b0 = bF[n], b1 = bF[n + 1];
                vt[nt * 2304 + c * 72 + i0]       = __float2half(acc[q][0] + b0);
                vt[nt * 2304 + (c + 1) * 72 + i0] = __float2half(acc[q][1] + b1);
                vt[nt * 2304 + c * 72 + i1]       = __float2half(acc[q][2] + b0);
                vt[nt * 2304 + (c + 1) * 72 + i1] = __float2half(acc[q][3] + b1);
            }
        } else {  // m == 0: Q in registers with rscale folded in
#pragma unroll
            for (int q = 0; q < 4; q++) {
                int n = nt * 32 + q * 8 + 2 * tg;
                float b0 = bF[n], b1 = bF[n + 1];
                qlo[q] = pack_h2((acc[q][0] + b0) * rscale, (acc[q][1] + b1) * rscale);
                qhi[q] = pack_h2((acc[q][2] + b0) * rscale, (acc[q][3] + b1) * rscale);
            }
        }
    }
    __syncthreads();  // K / V^T visible to all warps

    const int h = nt;
    const size_t tb = (size_t)b * N;

    // ---- scores: Q (register A-fragments, pre-scaled) x K^T ----
    float sc[8][4];
#pragma unroll
    for (int nn = 0; nn < 8; nn++)
#pragma unroll
        for (int r = 0; r < 4; r++) sc[nn][r] = 0.f;
    {
        const uint32_t kbase = sb + KOFF + h * 5120 + b_row * 80 + b_kb;
#pragma unroll
        for (int kc = 0; kc < 2; kc++) {
            uint32_t ah[4];
            ah[0] = qlo[2 * kc];
            ah[1] = qhi[2 * kc];
            ah[2] = qlo[2 * kc + 1];
            ah[3] = qhi[2 * kc + 1];
#pragma unroll
            for (int np = 0; np < 4; np++) {
                uint32_t bh[4];
                ldsm_x4(bh, kbase + (uint32_t)(np * 16 * 80) + kc * 32);
                mma16816f16(sc[2 * np],     ah, bh[0], bh[1]);
                mma16816f16(sc[2 * np + 1], ah, bh[2], bh[3]);
            }
        }
    }

    // ---- fix-up: coalesced fragment-ordered bias LDG + smem mask float2 ----
    const float2* b2 = g_bias2 + h * 2048 + mt * 512 + lane;  // + (nn*2+rp)*32
    const float2* mk2 = reinterpret_cast<const float2*>(sMask);
    const bool i0v = i0 < N, i1v = i1 < N;
#pragma unroll
    for (int nn = 0; nn < 8; nn++) {
        int jA = nn * 8 + 2 * tg;
        int jB = jA + 1;
        bool jAv = jA < N, jBv = jB < N;
        float2 fb0 = b2[(nn * 2 + 0) * 32];
        float2 fb1 = b2[(nn * 2 + 1) * 32];
        float2 fm0 = mk2[(i0 * 52 + jA) >> 1];
        float2 fm1 = mk2[(i1 * 52 + jA) >> 1];
        sc[nn][0] = (i0v && jAv) ? sc[nn][0] + fb0.x + fm0.x : -1e30f;
        sc[nn][1] = (i0v && jBv) ? sc[nn][1] + fb0.y + fm0.y : -1e30f;
        sc[nn][2] = (i1v && jAv) ? sc[nn][2] + fb1.x + fm1.x : -1e30f;
        sc[nn][3] = (i1v && jBv) ? sc[nn][3] + fb1.y + fm1.y : -1e30f;
    }

    // ---- register softmax ----
    float mx0 = -1e30f, mx1 = -1e30f;
#pragma unroll
    for (int nn = 0; nn < 8; nn++) {
        mx0 = fmaxf(mx0, fmaxf(sc[nn][0], sc[nn][1]));
        mx1 = fmaxf(mx1, fmaxf(sc[nn][2], sc[nn][3]));
    }
    mx0 = fmaxf(mx0, __shfl_xor_sync(0xffffffffu, mx0, 1));
    mx0 = fmaxf(mx0, __shfl_xor_sync(0xffffffffu, mx0, 2));
    mx1 = fmaxf(mx1, __shfl_xor_sync(0xffffffffu, mx1, 1));
    mx1 = fmaxf(mx1, __shfl_xor_sync(0xffffffffu, mx1, 2));

    float sum0 = 0.f, sum1 = 0.f;
#pragma unroll
    for (int nn = 0; nn < 8; nn++) {
        sc[nn][0] = __expf(sc[nn][0] - mx0);
        sc[nn][1] = __expf(sc[nn][1] - mx0);
        sc[nn][2] = __expf(sc[nn][2] - mx1);
        sc[nn][3] = __expf(sc[nn][3] - mx1);
        sum0 += sc[nn][0] + sc[nn][1];
        sum1 += sc[nn][2] + sc[nn][3];
    }
    sum0 += __shfl_xor_sync(0xffffffffu, sum0, 1);
    sum0 += __shfl_xor_sync(0xffffffffu, sum0, 2);
    sum1 += __shfl_xor_sync(0xffffffffu, sum1, 1);
    sum1 += __shfl_xor_sync(0xffffffffu, sum1, 2);
    const float inv0 = 1.0f / sum0;
    const float inv1 = 1.0f / sum1;

    // ---- ctx: P (register A-fragments) x V^T; direct coalesced-enough float2 STG ----
    float* ob = out + tb * CH + h * 32;
    const uint32_t vbase = sb + VTOFF + h * 4608 + b_row * 144 + b_kb;
#pragma unroll
    for (int np = 0; np < 2; np++) {
        float ct[2][4];
#pragma unroll
        for (int q = 0; q < 2; q++)
#pragma unroll
            for (int r = 0; r < 4; r++) ct[q][r] = 0.f;
#pragma unroll
        for (int kc = 0; kc < 4; kc++) {
            uint32_t a[4];
            a[0] = pack_h2(sc[2 * kc][0] * inv0,     sc[2 * kc][1] * inv0);
            a[1] = pack_h2(sc[2 * kc][2] * inv1,     sc[2 * kc][3] * inv1);
            a[2] = pack_h2(sc[2 * kc + 1][0] * inv0, sc[2 * kc + 1][1] * inv0);
            a[3] = pack_h2(sc[2 * kc + 1][2] * inv1, sc[2 * kc + 1][3] * inv1);
            uint32_t bh[4];
            ldsm_x4(bh, vbase + (uint32_t)(np * 16 * 144) + kc * 32);
            mma16816f16(ct[0], a, bh[0], bh[1]);
            mma16816f16(ct[1], a, bh[2], bh[3]);
        }
#pragma unroll
        for (int q = 0; q < 2; q++) {
            int c = np * 16 + q * 8 + 2 * tg;
            if (i0v)
                *reinterpret_cast<float2*>(&ob[i0 * CH + c]) = make_float2(ct[q][0], ct[q][1]);
            if (i1v)
                *reinterpret_cast<float2*>(&ob[i1 * CH + c]) = make_float2(ct[q][2], ct[q][3]);
        }
    }
}

// ============================ launch ============================
extern "C" void kernel_launch(void* const* d_in, const int* in_sizes, int n_in,
                              void* d_out, int out_size) {
    const float* hs    = (const float*)d_in[0];
    const float* mask  = (const float*)d_in[1];
    const float* Wq    = (const float*)d_in[2];
    const float* bq    = (const float*)d_in[3];
    const float* Wk    = (const float*)d_in[4];
    const float* bk    = (const float*)d_in[5];
    const float* Wv    = (const float*)d_in[6];
    const float* bv    = (const float*)d_in[7];
    const float* table = (const float*)d_in[8];
    const void*  idx   = (const void*)d_in[9];
    float* out = (float*)d_out;

    int B = in_sizes[0] / (N * CH);

    cudaFuncSetAttribute(fused_kernel, cudaFuncAttributeMaxDynamicSharedMemorySize,
                         FSMEM_BYTES);

    prep_kernel<<<7, 256>>>(Wq, Wk, Wv, table, idx);
    fused_kernel<<<B, 512, FSMEM_BYTES>>>(hs, mask, bq, bk, bv, out);
}